// round 4
// baseline (speedup 1.0000x reference)
#include <cuda_runtime.h>
#include <cuda_bf16.h>
#include <cstddef>

#define BATCH 64
#define SEQ   2048
#define INF   256
#define HID   512
#define OUTF  256
#define MROWS (BATCH * SEQ)   // 131072

// ---------------------------------------------------------------------------
// Scratch: sanctioned __device__ globals (no runtime allocation)
// ---------------------------------------------------------------------------
__device__ float g_xproj[(size_t)MROWS * HID];   // x @ W1_x + b1, row m = b*SEQ + t
__device__ float g_hall [(size_t)MROWS * HID];   // h_t, row m = b*SEQ + t

// Per-row-group barrier state (8 groups of 16 CTAs). Generation counter is
// free-running; after a full run cnt==0 and gen is uniform per group, so
// graph replays need no reset.
__device__ unsigned int g_cnt[8];
__device__ unsigned int g_gen[8];

// ---------------------------------------------------------------------------
// Tiled fp32 GEMM + bias: C[M,N] = A[M,K] @ B[K,N] + bias[N]
// BM=BN=128, BK=16, 256 threads, 8x8 per thread. K,N multiples of 16/128.
// ---------------------------------------------------------------------------
template<int K, int N>
__global__ void __launch_bounds__(256, 1)
gemm_bias(const float* __restrict__ A,
          const float* __restrict__ Bm,
          const float* __restrict__ bias,
          float* __restrict__ C)
{
    __shared__ float As[16][128];
    __shared__ float Bs[16][128];

    const int tid = threadIdx.x;
    const int tx  = tid & 15;          // output col group
    const int ty  = tid >> 4;          // output row group
    const int cm0 = blockIdx.y * 128;
    const int cn0 = blockIdx.x * 128;

    float acc[8][8];
#pragma unroll
    for (int i = 0; i < 8; ++i)
#pragma unroll
        for (int j = 0; j < 8; ++j) acc[i][j] = 0.0f;

    for (int k0 = 0; k0 < K; k0 += 16) {
        // A tile (128 rows x 16 k) -> As[k][m] (transposed)
#pragma unroll
        for (int f = 0; f < 2; ++f) {
            int linear = tid + 256 * f;            // 512 float4 slots
            int m  = linear >> 2;                  // 0..127
            int kq = linear & 3;                   // 0..3
            float4 av = *reinterpret_cast<const float4*>(
                &A[(size_t)(cm0 + m) * K + k0 + kq * 4]);
            As[kq * 4 + 0][m] = av.x;
            As[kq * 4 + 1][m] = av.y;
            As[kq * 4 + 2][m] = av.z;
            As[kq * 4 + 3][m] = av.w;
        }
        // B tile (16 k x 128 n) -> Bs[k][n]
#pragma unroll
        for (int f = 0; f < 2; ++f) {
            int linear = tid + 256 * f;
            int kk = linear >> 5;                  // 0..15
            int nq = linear & 31;                  // 0..31
            *reinterpret_cast<float4*>(&Bs[kk][nq * 4]) =
                *reinterpret_cast<const float4*>(
                    &Bm[(size_t)(k0 + kk) * N + cn0 + nq * 4]);
        }
        __syncthreads();

#pragma unroll
        for (int kk = 0; kk < 16; ++kk) {
            float a[8], b[8];
            *reinterpret_cast<float4*>(&a[0]) =
                *reinterpret_cast<const float4*>(&As[kk][ty * 8]);
            *reinterpret_cast<float4*>(&a[4]) =
                *reinterpret_cast<const float4*>(&As[kk][ty * 8 + 4]);
            *reinterpret_cast<float4*>(&b[0]) =
                *reinterpret_cast<const float4*>(&Bs[kk][tx * 8]);
            *reinterpret_cast<float4*>(&b[4]) =
                *reinterpret_cast<const float4*>(&Bs[kk][tx * 8 + 4]);
#pragma unroll
            for (int i = 0; i < 8; ++i)
#pragma unroll
                for (int j = 0; j < 8; ++j)
                    acc[i][j] = fmaf(a[i], b[j], acc[i][j]);
        }
        __syncthreads();
    }

    float bv[8];
#pragma unroll
    for (int j = 0; j < 8; ++j) bv[j] = bias[cn0 + tx * 8 + j];

#pragma unroll
    for (int i = 0; i < 8; ++i) {
        size_t row = (size_t)(cm0 + ty * 8 + i);
        float4 o0, o1;
        o0.x = acc[i][0] + bv[0]; o0.y = acc[i][1] + bv[1];
        o0.z = acc[i][2] + bv[2]; o0.w = acc[i][3] + bv[3];
        o1.x = acc[i][4] + bv[4]; o1.y = acc[i][5] + bv[5];
        o1.z = acc[i][6] + bv[6]; o1.w = acc[i][7] + bv[7];
        *reinterpret_cast<float4*>(&C[row * N + cn0 + tx * 8])     = o0;
        *reinterpret_cast<float4*>(&C[row * N + cn0 + tx * 8 + 4]) = o1;
    }
}

// ---------------------------------------------------------------------------
// Persistent recurrent kernel.
// 128 CTAs = 8 row-groups (gb: 8 batch rows) x 16 col-groups (gc: 32 cols).
// Dynamic SMEM: Wsm[c][k] 512*32 floats (64KB) + hsm[r][k] 8*512 floats (16KB).
// Warp tile 4 rows x 8 cols, k spread across lanes (16 phases of 32 k).
// 31-shuffle compacting butterfly: lane l ends with the full sum for flat
// output index l -> (row r0 + (l>>3), col c0 + (l&7)).
// Per-step 16-CTA sense-reversing barrier via L2 atomics.
// ---------------------------------------------------------------------------
__global__ void __launch_bounds__(256, 1)
rnn_recurrent(const float* __restrict__ W1)
{
    extern __shared__ float sm[];
    float* Wsm = sm;                 // [32 cols][512 k]
    float* hsm = sm + 512 * 32;      // [8 rows][512 k]

    const int tid = threadIdx.x;
    const int gb  = blockIdx.x >> 4;     // 0..7  row group
    const int gc  = blockIdx.x & 15;     // 0..15 col group
    const int rb  = gb * 8;              // batch row base
    const int cb  = gc * 32;             // hidden col base

    // Preload W1_h column slice: Wsm[c*512 + k] = W1[k][cb + c]
    for (int idx = tid; idx < 512 * 32; idx += 256) {
        int k = idx >> 5, c = idx & 31;
        Wsm[c * 512 + k] = W1[(size_t)k * 512 + cb + c];
    }

    const int lane = tid & 31;
    const int w    = tid >> 5;
    const int r0   = (w >> 2) * 4;        // 0 or 4
    const int c0   = (w & 3) * 8;         // 0,8,16,24
    const int orow = r0 + (lane >> 3);    // my output row within tile (0..7)
    const int ocol = c0 + (lane & 7);     // my output col within tile (0..31)

    const size_t out_base = ((size_t)(rb + orow) * SEQ) * HID + cb + ocol;

    __syncthreads();

    for (int t = 0; t < SEQ; ++t) {
        float xp = __ldg(&g_xproj[out_base + (size_t)t * HID]);
        float v;

        if (t == 0) {
            v = tanhf(xp);                 // h0 == 0
        } else {
            // Stage h_{t-1} rows rb..rb+7 (16KB) into SMEM via L2
#pragma unroll
            for (int q = 0; q < 4; ++q) {
                int f  = tid + 256 * q;    // 1024 float4 slots
                int r  = f >> 7;           // 0..7
                int kq = f & 127;          // 0..127
                const float4* src = reinterpret_cast<const float4*>(
                    &g_hall[(((size_t)(rb + r) * SEQ) + (t - 1)) * HID + kq * 4]);
                *reinterpret_cast<float4*>(&hsm[r * 512 + kq * 4]) = __ldcg(src);
            }
            __syncthreads();

            float acc[32];
#pragma unroll
            for (int a = 0; a < 32; ++a) acc[a] = 0.0f;

#pragma unroll 4
            for (int p = 0; p < 16; ++p) {
                int k = p * 32 + lane;
                float hr[4];
#pragma unroll
                for (int i = 0; i < 4; ++i) hr[i] = hsm[(r0 + i) * 512 + k];
                float wr[8];
#pragma unroll
                for (int j = 0; j < 8; ++j) wr[j] = Wsm[(c0 + j) * 512 + k];
#pragma unroll
                for (int i = 0; i < 4; ++i)
#pragma unroll
                    for (int j = 0; j < 8; ++j)
                        acc[i * 8 + j] = fmaf(hr[i], wr[j], acc[i * 8 + j]);
            }

            // Compacting butterfly reduce: lane l -> total sum of acc[l]
#pragma unroll
            for (int off = 16; off > 0; off >>= 1) {
                bool up = (lane & off) != 0;
#pragma unroll
                for (int a = 0; a < 16; ++a) {
                    if (a >= off) continue;
                    float send = up ? acc[a] : acc[a + off];
                    float recv = __shfl_xor_sync(0xffffffffu, send, off);
                    float keep = up ? acc[a + off] : acc[a];
                    acc[a] = keep + recv;
                }
            }
            v = tanhf(acc[0] + xp);
            __syncthreads();   // hsm reuse safety for next iteration
        }

        g_hall[out_base + (size_t)t * HID] = v;

        // ---- per-row-group barrier (16 CTAs) ----
        __syncthreads();                   // all h writes of this CTA issued
        if (tid == 0) {
            __threadfence();               // publish h writes
            unsigned gen = *((volatile unsigned int*)&g_gen[gb]);
            unsigned old = atomicAdd(&g_cnt[gb], 1u);
            if (old == 15u) {
                atomicExch(&g_cnt[gb], 0u);
                __threadfence();
                atomicAdd(&g_gen[gb], 1u);
            } else {
                while (*((volatile unsigned int*)&g_gen[gb]) == gen) { }
                __threadfence();           // acquire
            }
        }
        __syncthreads();                   // release whole CTA into step t+1
    }
}

// ---------------------------------------------------------------------------
// h_last: dst[b*512 + c] = g_hall[b, SEQ-1, c]
// ---------------------------------------------------------------------------
__global__ void copy_hlast(float* __restrict__ dst)
{
    int i = blockIdx.x * 256 + threadIdx.x;     // 0..32767
    int b = i >> 9;
    int c = i & 511;
    dst[i] = g_hall[(((size_t)b * SEQ) + (SEQ - 1)) * HID + c];
}

// ---------------------------------------------------------------------------
// Launch
// ---------------------------------------------------------------------------
extern "C" void kernel_launch(void* const* d_in, const int* in_sizes, int n_in,
                              void* d_out, int out_size)
{
    const float* x  = (const float*)d_in[0];   // (64, 2048, 256)
    const float* W1 = (const float*)d_in[1];   // (768, 512): [0:512]=W1_h, [512:768]=W1_x
    const float* b1 = (const float*)d_in[2];   // (512,)
    const float* W2 = (const float*)d_in[3];   // (512, 256)
    const float* b2 = (const float*)d_in[4];   // (256,)
    float* out = (float*)d_out;

    float* xproj = nullptr;
    float* hall  = nullptr;
    cudaGetSymbolAddress((void**)&xproj, g_xproj);
    cudaGetSymbolAddress((void**)&hall,  g_hall);

    const int smem_bytes = (512 * 32 + 8 * 512) * (int)sizeof(float);  // 81920
    cudaFuncSetAttribute(rnn_recurrent,
                         cudaFuncAttributeMaxDynamicSharedMemorySize, smem_bytes);

    // 1) xproj = x @ W1_x + b1   (M=131072, K=256, N=512)
    {
        dim3 grid(HID / 128, MROWS / 128);
        gemm_bias<INF, HID><<<grid, 256>>>(x, W1 + (size_t)HID * HID, b1, xproj);
    }

    // 2) recurrence: h_t = tanh(h_{t-1} @ W1_h + xproj_t)
    rnn_recurrent<<<128, 256, smem_bytes>>>(W1);

    // 3) output = hall @ W2 + b2  (M=131072, K=512, N=256)
    {
        dim3 grid(OUTF / 128, MROWS / 128);
        gemm_bias<HID, OUTF><<<grid, 256>>>(hall, W2, b2, out);
    }

    // 4) h_last -> tail of d_out
    {
        size_t hlast_off = (size_t)out_size - (size_t)BATCH * HID;
        copy_hlast<<<(BATCH * HID) / 256, 256>>>(out + hlast_off);
    }
}

// round 6
// speedup vs baseline: 1.1194x; 1.1194x over previous
#include <cuda_runtime.h>
#include <cuda_bf16.h>
#include <cstddef>
#include <cstdint>

#define BATCH 64
#define SEQ   2048
#define INF   256
#define HID   512
#define OUTF  256
#define MROWS (BATCH * SEQ)   // 131072

// ---------------------------------------------------------------------------
// Scratch: sanctioned __device__ globals
// ---------------------------------------------------------------------------
__device__ float g_xproj[(size_t)MROWS * HID];   // x @ W1_x + b1, row m = b*SEQ + t
__device__ float g_hall [(size_t)MROWS * HID];   // h_t, row m = b*SEQ + t

// ---------------------------------------------------------------------------
// PTX helpers
// ---------------------------------------------------------------------------
__device__ __forceinline__ uint32_t smem_u32(const void* p) {
    uint32_t a;
    asm("{ .reg .u64 t; cvta.to.shared.u64 t, %1; cvt.u32.u64 %0, t; }"
        : "=r"(a) : "l"(p));
    return a;
}
__device__ __forceinline__ uint32_t cluster_rank() {
    uint32_t r; asm("mov.u32 %0, %%cluster_ctarank;" : "=r"(r)); return r;
}
__device__ __forceinline__ uint32_t mapa_cluster(uint32_t local, uint32_t rank) {
    uint32_t r;
    asm("mapa.shared::cluster.u32 %0, %1, %2;" : "=r"(r) : "r"(local), "r"(rank));
    return r;
}
__device__ __forceinline__ void st_cluster_f32(uint32_t addr, float v) {
    asm volatile("st.shared::cluster.f32 [%0], %1;" :: "r"(addr), "f"(v));
}
__device__ __forceinline__ void cluster_sync() {
    asm volatile("barrier.cluster.arrive.aligned;" ::: "memory");
    asm volatile("barrier.cluster.wait.aligned;"   ::: "memory");
}
// Packed dual-fp32 FMA: d = a*b + d (elementwise on 2 packed floats)
__device__ __forceinline__ void ffma2(unsigned long long& d,
                                      unsigned long long a,
                                      unsigned long long b) {
    asm("fma.rn.f32x2 %0, %1, %2, %0;" : "+l"(d) : "l"(a), "l"(b));
}

// ---------------------------------------------------------------------------
// Tiled fp32 GEMM + bias: C[M,N] = A[M,K] @ B[K,N] + bias[N]
// (unchanged from R3 -- known correct)
// ---------------------------------------------------------------------------
template<int K, int N>
__global__ void __launch_bounds__(256, 1)
gemm_bias(const float* __restrict__ A,
          const float* __restrict__ Bm,
          const float* __restrict__ bias,
          float* __restrict__ C)
{
    __shared__ float As[16][128];
    __shared__ float Bs[16][128];

    const int tid = threadIdx.x;
    const int tx  = tid & 15;
    const int ty  = tid >> 4;
    const int cm0 = blockIdx.y * 128;
    const int cn0 = blockIdx.x * 128;

    float acc[8][8];
#pragma unroll
    for (int i = 0; i < 8; ++i)
#pragma unroll
        for (int j = 0; j < 8; ++j) acc[i][j] = 0.0f;

    for (int k0 = 0; k0 < K; k0 += 16) {
#pragma unroll
        for (int f = 0; f < 2; ++f) {
            int linear = tid + 256 * f;
            int m  = linear >> 2;
            int kq = linear & 3;
            float4 av = *reinterpret_cast<const float4*>(
                &A[(size_t)(cm0 + m) * K + k0 + kq * 4]);
            As[kq * 4 + 0][m] = av.x;
            As[kq * 4 + 1][m] = av.y;
            As[kq * 4 + 2][m] = av.z;
            As[kq * 4 + 3][m] = av.w;
        }
#pragma unroll
        for (int f = 0; f < 2; ++f) {
            int linear = tid + 256 * f;
            int kk = linear >> 5;
            int nq = linear & 31;
            *reinterpret_cast<float4*>(&Bs[kk][nq * 4]) =
                *reinterpret_cast<const float4*>(
                    &Bm[(size_t)(k0 + kk) * N + cn0 + nq * 4]);
        }
        __syncthreads();

#pragma unroll
        for (int kk = 0; kk < 16; ++kk) {
            float a[8], b[8];
            *reinterpret_cast<float4*>(&a[0]) =
                *reinterpret_cast<const float4*>(&As[kk][ty * 8]);
            *reinterpret_cast<float4*>(&a[4]) =
                *reinterpret_cast<const float4*>(&As[kk][ty * 8 + 4]);
            *reinterpret_cast<float4*>(&b[0]) =
                *reinterpret_cast<const float4*>(&Bs[kk][tx * 8]);
            *reinterpret_cast<float4*>(&b[4]) =
                *reinterpret_cast<const float4*>(&Bs[kk][tx * 8 + 4]);
#pragma unroll
            for (int i = 0; i < 8; ++i)
#pragma unroll
                for (int j = 0; j < 8; ++j)
                    acc[i][j] = fmaf(a[i], b[j], acc[i][j]);
        }
        __syncthreads();
    }

    float bv[8];
#pragma unroll
    for (int j = 0; j < 8; ++j) bv[j] = bias[cn0 + tx * 8 + j];

#pragma unroll
    for (int i = 0; i < 8; ++i) {
        size_t row = (size_t)(cm0 + ty * 8 + i);
        float4 o0, o1;
        o0.x = acc[i][0] + bv[0]; o0.y = acc[i][1] + bv[1];
        o0.z = acc[i][2] + bv[2]; o0.w = acc[i][3] + bv[3];
        o1.x = acc[i][4] + bv[4]; o1.y = acc[i][5] + bv[5];
        o1.z = acc[i][6] + bv[6]; o1.w = acc[i][7] + bv[7];
        *reinterpret_cast<float4*>(&C[row * N + cn0 + tx * 8])     = o0;
        *reinterpret_cast<float4*>(&C[row * N + cn0 + tx * 8 + 4]) = o1;
    }
}

// ---------------------------------------------------------------------------
// Cluster-based persistent recurrent kernel.
//
// 128 CTAs = 16 row-groups (4 batch rows) x 8 col-groups (64 hidden cols).
// Each row-group's 8 CTAs = one CGA cluster (rank == col-group).
// SMEM: Wsm [64 cols][512 k] = 128KB + h double buffer 2x(4x512 f) = 16KB.
//
// k layout: 512 k = 256 pairs; lane l, phase p -> pair p*32 + l
//   => byte offset within a 2048-byte row: kb = 8*lane + 256*p   (p = 0..7)
//   (R4 bug: used 1024*p -> SMEM OOB trap. Fixed.)
// Bounds: row base + kb <= 2040+8 = 2048 ✓; max smem read = 147456 exactly.
//
// Warp tile 4 rows x 8 cols; phases 0..3 of W cached in 64 regs.
// 31-shuffle compacting butterfly (verified in R3): lane l ends with the full
// sum for tile index l -> (row l>>3, col w*8 + (l&7)).
// h exchange: each thread pushes its h value into all 8 peers' buffer (t&1)
// via st.shared::cluster; one barrier.cluster per step (release/acquire).
// ---------------------------------------------------------------------------
#define WSM_FLOATS  (64 * 512)      // 32768 floats = 131072 B
#define HBUF_FLOATS (4 * 512)       // 2048 floats  = 8192 B per buffer
#define RNN_SMEM_BYTES ((WSM_FLOATS + 2 * HBUF_FLOATS) * 4)   // 147456

__global__ void __launch_bounds__(256, 1) __cluster_dims__(8, 1, 1)
rnn_recurrent(const float* __restrict__ W1)
{
    extern __shared__ float sm[];
    float* Wsm  = sm;                         // [c*512 + k]
    float* hbuf = sm + WSM_FLOATS;            // [parity][row*512 + gcol]

    const int tid   = threadIdx.x;
    const int lane  = tid & 31;
    const int w     = tid >> 5;               // warp 0..7
    const uint32_t rank = cluster_rank();     // 0..7 = col group
    const int gb    = blockIdx.x >> 3;        // 0..15 row group
    const int rb    = gb * 4;                 // batch row base
    const int cb    = (int)rank * 64;         // hidden col base

    // Load W1_h col slice: Wsm[c*512 + k] = W1[k][cb + c]  (coalesced LDG)
    for (int idx = tid; idx < WSM_FLOATS; idx += 256) {
        int c = idx & 63, k = idx >> 6;
        Wsm[c * 512 + k] = W1[(size_t)k * 512 + cb + c];
    }
    __syncthreads();

    // Per-thread geometry
    const int orow = lane >> 3;               // 0..3
    const int ocol = w * 8 + (lane & 7);      // 0..63 local col
    const int gcol = cb + ocol;               // global hidden col
    const size_t xp_base =
        ((size_t)(rb + orow) * SEQ) * HID + gcol;
    const int koff0 = 8 * lane;               // lane byte offset (0..248)

    // Register cache of W for phases 0..3 (kb = koff0 + 256*p, p<4)
    unsigned long long wc[4][8];
#pragma unroll
    for (int p = 0; p < 4; ++p)
#pragma unroll
        for (int j = 0; j < 8; ++j)
            wc[p][j] = *reinterpret_cast<const unsigned long long*>(
                reinterpret_cast<const char*>(&Wsm[(w * 8 + j) * 512]) +
                koff0 + p * 256);

    // Peer hbuf base addresses (shared::cluster window)
    uint32_t hbase_local = smem_u32(hbuf);
    uint32_t peer_base[8];
#pragma unroll
    for (int pr = 0; pr < 8; ++pr)
        peer_base[pr] = mapa_cluster(hbase_local, (uint32_t)pr);
    const uint32_t my_off = (uint32_t)(orow * 512 + gcol) * 4u;  // <= 8188

    for (int t = 0; t < SEQ; ++t) {
        float xp = __ldg(&g_xproj[xp_base + (size_t)t * HID]);   // hidden under compute
        float v;

        if (t == 0) {
            v = tanhf(xp);                    // h0 == 0
        } else {
            const char* hprev = reinterpret_cast<const char*>(
                hbuf + ((t & 1) ^ 1) * HBUF_FLOATS);

            unsigned long long acc[32];
#pragma unroll
            for (int a = 0; a < 32; ++a) acc[a] = 0ull;

#pragma unroll
            for (int p = 0; p < 8; ++p) {
                const int kb = koff0 + p * 256;           // 0..2040, 8B aligned
                unsigned long long h2[4];
#pragma unroll
                for (int i = 0; i < 4; ++i)
                    h2[i] = *reinterpret_cast<const unsigned long long*>(
                        hprev + i * 2048 + kb);
                if (p < 4) {
#pragma unroll
                    for (int i = 0; i < 4; ++i)
#pragma unroll
                        for (int j = 0; j < 8; ++j)
                            ffma2(acc[i * 8 + j], h2[i], wc[p][j]);
                } else {
                    unsigned long long w2[8];
#pragma unroll
                    for (int j = 0; j < 8; ++j)
                        w2[j] = *reinterpret_cast<const unsigned long long*>(
                            reinterpret_cast<const char*>(&Wsm[(w * 8 + j) * 512]) + kb);
#pragma unroll
                    for (int i = 0; i < 4; ++i)
#pragma unroll
                        for (int j = 0; j < 8; ++j)
                            ffma2(acc[i * 8 + j], h2[i], w2[j]);
                }
            }

            // Collapse f32x2 halves -> 32 scalars
            float s[32];
#pragma unroll
            for (int a = 0; a < 32; ++a) {
                float2 f = *reinterpret_cast<float2*>(&acc[a]);
                s[a] = f.x + f.y;
            }

            // Compacting butterfly: lane l ends with full sum for index l
#pragma unroll
            for (int off = 16; off > 0; off >>= 1) {
                bool up = (lane & off) != 0;
#pragma unroll
                for (int a = 0; a < 16; ++a) {
                    if (a >= off) continue;
                    float send = up ? s[a] : s[a + off];
                    float recv = __shfl_xor_sync(0xffffffffu, send, off);
                    float keep = up ? s[a + off] : s[a];
                    s[a] = keep + recv;
                }
            }
            v = tanhf(s[0] + xp);
        }

        // Store h_t for the post-GEMM
        g_hall[xp_base + (size_t)t * HID] = v;

        // Push v into every cluster CTA's buffer (t&1)
        const uint32_t doff = (uint32_t)((t & 1) * (HBUF_FLOATS * 4)) + my_off;
#pragma unroll
        for (int pr = 0; pr < 8; ++pr)
            st_cluster_f32(peer_base[pr] + doff, v);

        // One cluster barrier per step (arrive=release, wait=acquire):
        // orders this step's pushes before next step's reads, and prevents
        // next step's pushes from racing a slow peer's current reads.
        cluster_sync();
    }
}

// ---------------------------------------------------------------------------
// h_last: dst[b*512 + c] = g_hall[b, SEQ-1, c]
// ---------------------------------------------------------------------------
__global__ void copy_hlast(float* __restrict__ dst)
{
    int i = blockIdx.x * 256 + threadIdx.x;     // 0..32767
    int b = i >> 9;
    int c = i & 511;
    dst[i] = g_hall[(((size_t)b * SEQ) + (SEQ - 1)) * HID + c];
}

// ---------------------------------------------------------------------------
// Launch
// ---------------------------------------------------------------------------
extern "C" void kernel_launch(void* const* d_in, const int* in_sizes, int n_in,
                              void* d_out, int out_size)
{
    const float* x  = (const float*)d_in[0];   // (64, 2048, 256)
    const float* W1 = (const float*)d_in[1];   // (768, 512): [0:512]=W1_h, [512:768]=W1_x
    const float* b1 = (const float*)d_in[2];   // (512,)
    const float* W2 = (const float*)d_in[3];   // (512, 256)
    const float* b2 = (const float*)d_in[4];   // (256,)
    float* out = (float*)d_out;

    float* xproj = nullptr;
    float* hall  = nullptr;
    cudaGetSymbolAddress((void**)&xproj, g_xproj);
    cudaGetSymbolAddress((void**)&hall,  g_hall);

    cudaFuncSetAttribute(rnn_recurrent,
                         cudaFuncAttributeMaxDynamicSharedMemorySize,
                         RNN_SMEM_BYTES);

    // 1) xproj = x @ W1_x + b1   (M=131072, K=256, N=512)
    {
        dim3 grid(HID / 128, MROWS / 128);
        gemm_bias<INF, HID><<<grid, 256>>>(x, W1 + (size_t)HID * HID, b1, xproj);
    }

    // 2) recurrence: h_t = tanh(h_{t-1} @ W1_h + xproj_t)
    rnn_recurrent<<<128, 256, RNN_SMEM_BYTES>>>(W1);

    // 3) output = hall @ W2 + b2  (M=131072, K=512, N=256)
    {
        dim3 grid(OUTF / 128, MROWS / 128);
        gemm_bias<HID, OUTF><<<grid, 256>>>(hall, W2, b2, out);
    }

    // 4) h_last -> tail of d_out
    {
        size_t hlast_off = (size_t)out_size - (size_t)BATCH * HID;
        copy_hlast<<<(BATCH * HID) / 256, 256>>>(out + hlast_off);
    }
}